// round 3
// baseline (speedup 1.0000x reference)
#include <cuda_runtime.h>
#include <cstdint>

#define HH 400
#define WW 400
#define CC 128
#define KS 25
#define PP 12
#define NPIX (HH*WW)

// ---------------- device scratch (no allocations allowed) ----------------
__device__ float g_cubeT[(size_t)CC * NPIX + 1024];   // channel-major transpose (+pad for window overreach)
__device__ float g_norm[NPIX + 64];                   // per-pixel L2 norm (+pad)
__device__ unsigned int g_max_u;                      // global max of edge (non-negative float as uint)

// ---------------- helpers ----------------
__device__ __forceinline__ float kweight(int i, int j) {
    // Kx[i][j] from reference _generate_kernel (rows mirrored about 12, antisymmetric in j)
    int ii = min(i, 24 - i);
    if (j < 12) return (float)(j - 12 - ii);
    if (j > 12) return (float)(j - 12 + ii);
    return 0.0f;
}

__device__ __forceinline__ float acos_poly(float x) {
    // Abramowitz & Stegun 4.4.46, |err| ~<= 1e-7 in fp32
    float ax = fabsf(x);
    float p = fmaf(ax, -0.0012624911f, 0.0066700901f);
    p = fmaf(p, ax, -0.0170881256f);
    p = fmaf(p, ax,  0.0308918810f);
    p = fmaf(p, ax, -0.0501743046f);
    p = fmaf(p, ax,  0.0889789874f);
    p = fmaf(p, ax, -0.2145988016f);
    p = fmaf(p, ax,  1.5707963050f);
    float om = 1.0f - ax;
    float s;
    asm("sqrt.approx.f32 %0, %1;" : "=f"(s) : "f"(om));
    float t = s * p;
    return (x < 0.0f) ? (3.14159265358979f - t) : t;
}

// ---------------- K1: transpose pixel-major -> channel-major ----------------
__global__ void k_transpose(const float* __restrict__ cube) {
    __shared__ float tile[32][CC + 4];
    int px0 = blockIdx.x * 32;
    int t = threadIdx.x;                 // 256 threads
    {
        int lp = t >> 3;                 // 0..31 local pixel
        int cb = (t & 7) << 4;           // channel base 0,16,...,112
        const float4* src = reinterpret_cast<const float4*>(cube + (size_t)(px0 + lp) * CC + cb);
        #pragma unroll
        for (int q = 0; q < 4; q++) {
            float4 v = src[q];
            tile[lp][cb + 4*q + 0] = v.x;
            tile[lp][cb + 4*q + 1] = v.y;
            tile[lp][cb + 4*q + 2] = v.z;
            tile[lp][cb + 4*q + 3] = v.w;
        }
    }
    __syncthreads();
    int lane = t & 31;
    int crow = t >> 5;                   // 0..7
    #pragma unroll
    for (int it = 0; it < 16; it++) {
        int c = it * 8 + crow;
        g_cubeT[(size_t)c * NPIX + px0 + lane] = tile[lane][c];
    }
    if (blockIdx.x == 0 && t == 0) g_max_u = 0u;
}

// ---------------- K2: per-pixel norms ----------------
__global__ void k_norm() {
    int px = blockIdx.x * blockDim.x + threadIdx.x;
    if (px >= NPIX) return;
    float s = 0.0f;
    #pragma unroll 8
    for (int c = 0; c < CC; c++) {
        float v = g_cubeT[(size_t)c * NPIX + px];
        s = fmaf(v, v, s);
    }
    g_norm[px] = sqrtf(s);
}

// ---------------- K3: main edge kernel ----------------
// Grid: (3, 47). CTA: 256 threads = 8 warps; warp = tile row; lane handles 4 consecutive cols.
// Tile: 8 rows x 128 cols of interior pixels. Interior rows/cols: [12, 388).
__global__ void __launch_bounds__(256, 1) k_edge(float* __restrict__ out) {
    __shared__ float skx[KS*KS], sky[KS*KS];
    __shared__ unsigned int blkmax;
    int t = threadIdx.x;
    if (t == 0) blkmax = 0u;
    for (int i = t; i < KS*KS; i += 256) {
        int di = i / KS, dj = i % KS;
        skx[i] = kweight(di, dj);       // Kx[di][dj]
        sky[i] = kweight(dj, di);       // Ky[di][dj] = Kx[dj][di]
    }
    __syncthreads();

    int wrp = t >> 5;
    int tx  = t & 31;
    int r   = 12 + blockIdx.y * 8 + wrp;          // center row (12..387)
    int cb  = 12 + blockIdx.x * 128 + tx * 4;     // center col base
    bool valid = (cb + 3) <= 387;                 // last tile: lanes 30,31 masked (376 = 128+128+120)

    float4 nc4 = *reinterpret_cast<const float4*>(&g_norm[r * WW + cb]);
    float ncv[4] = {nc4.x, nc4.y, nc4.z, nc4.w};

    float gx[4] = {0,0,0,0};
    float gy[4] = {0,0,0,0};

    const float* __restrict__ bc = g_cubeT + (size_t)r * WW + cb;      // center, per-channel stride NPIX

    #pragma unroll 1
    for (int di = 0; di < KS; di++) {
        int srow = r + di - 12;                                        // 0..399
        const float* __restrict__ bs = g_cubeT + (size_t)srow * WW + (cb - 12);

        float acc[4][KS];
        #pragma unroll
        for (int p = 0; p < 4; p++)
            #pragma unroll
            for (int dj = 0; dj < KS; dj++) acc[p][dj] = 0.0f;

        #pragma unroll 2
        for (int c = 0; c < CC; c++) {
            size_t coff = (size_t)c * NPIX;
            float4 ct4 = *reinterpret_cast<const float4*>(bc + coff);
            float ctr[4] = {ct4.x, ct4.y, ct4.z, ct4.w};
            float s[28];
            #pragma unroll
            for (int j = 0; j < 7; j++) {
                float4 v = *reinterpret_cast<const float4*>(bs + coff + 4*j);
                s[4*j + 0] = v.x; s[4*j + 1] = v.y; s[4*j + 2] = v.z; s[4*j + 3] = v.w;
            }
            #pragma unroll
            for (int p = 0; p < 4; p++)
                #pragma unroll
                for (int dj = 0; dj < KS; dj++)
                    acc[p][dj] = fmaf(ctr[p], s[p + dj], acc[p][dj]);
        }

        // epilogue for this di: ratio -> acos -> weighted accumulation
        const float* __restrict__ nrow = g_norm + (size_t)srow * WW + (cb - 12);
        float ns[28];
        #pragma unroll
        for (int j = 0; j < 7; j++) {
            float4 v = *reinterpret_cast<const float4*>(nrow + 4*j);
            ns[4*j + 0] = v.x; ns[4*j + 1] = v.y; ns[4*j + 2] = v.z; ns[4*j + 3] = v.w;
        }
        #pragma unroll
        for (int dj = 0; dj < KS; dj++) {
            float kxv = skx[di*KS + dj];
            float kyv = sky[di*KS + dj];
            #pragma unroll
            for (int p = 0; p < 4; p++) {
                float den = fmaf(ncv[p], ns[p + dj], 1e-4f);
                float ratio = __fdividef(acc[p][dj], den);
                ratio = fminf(fmaxf(ratio, -1.0f + 1e-6f), 1.0f - 1e-6f);
                float sad = acos_poly(ratio);
                gx[p] = fmaf(sad, kxv, gx[p]);
                gy[p] = fmaf(sad, kyv, gy[p]);
            }
        }
    }

    if (valid) {
        float4 e;
        e.x = fabsf(gx[0]) + fabsf(gy[0]);
        e.y = fabsf(gx[1]) + fabsf(gy[1]);
        e.z = fabsf(gx[2]) + fabsf(gy[2]);
        e.w = fabsf(gx[3]) + fabsf(gy[3]);
        *reinterpret_cast<float4*>(out + (size_t)r * WW + cb) = e;
        float m = fmaxf(fmaxf(e.x, e.y), fmaxf(e.z, e.w));
        atomicMax(&blkmax, __float_as_uint(m));
    }
    __syncthreads();
    if (t == 0) atomicMax(&g_max_u, blkmax);
}

// ---------------- K4: normalize + zero border ----------------
__global__ void k_final(float* __restrict__ out) {
    int idx = blockIdx.x * blockDim.x + threadIdx.x;
    if (idx >= NPIX) return;
    int h = idx / WW;
    int w = idx - h * WW;
    float m = __uint_as_float(g_max_u);
    if (h >= 12 && h < 388 && w >= 12 && w < 388) {
        out[idx] = out[idx] / m;
    } else {
        out[idx] = 0.0f;
    }
}

// ---------------- launch ----------------
extern "C" void kernel_launch(void* const* d_in, const int* in_sizes, int n_in,
                              void* d_out, int out_size) {
    const float* cube = (const float*)d_in[0];
    float* out = (float*)d_out;

    k_transpose<<<NPIX / 32, 256>>>(cube);
    k_norm<<<(NPIX + 255) / 256, 256>>>();
    {
        dim3 grid(3, 47);
        k_edge<<<grid, 256>>>(out);
    }
    k_final<<<(NPIX + 255) / 256, 256>>>(out);
}